// round 13
// baseline (speedup 1.0000x reference)
#include <cuda_runtime.h>
#include <math.h>
#include <stdint.h>

#define B_    8
#define LQ_   512
#define LK_   2048
#define E_    512
#define H_    8
#define HD_   64
#define TOPK_ 20

// ---------------- scratch (static device globals; no allocs) ----------------
__device__ __align__(128) float g_Qh[(size_t)B_ * H_ * LQ_ * HD_];   //  8 MB  [b,h,lq,hd]  (tf32-rounded)
__device__ __align__(128) float g_Kh[(size_t)B_ * H_ * LK_ * HD_];   // 32 MB  [b,h,lk,hd]  (tf32-rounded)
__device__ __align__(128) float g_Vh[(size_t)B_ * H_ * LK_ * HD_];   // 32 MB  [b,h,lk,hd]
__device__ __align__(128) float g_AO[(size_t)B_ * LQ_ * E_];         //  8 MB  [b,lq,e]

// ======================= mma.sync helpers (base ISA) ========================
__device__ __forceinline__ uint32_t smem_u32(const void* p) {
    uint32_t a;
    asm("{ .reg .u64 t; cvta.to.shared.u64 t, %1; cvt.u32.u64 %0, t; }" : "=r"(a) : "l"(p));
    return a;
}
__device__ __forceinline__ uint32_t cvt_tf32(float x) {
    uint32_t r;
    asm("cvt.rna.tf32.f32 %0, %1;" : "=r"(r) : "f"(x));
    return r;
}
__device__ __forceinline__ void ldsm_x4(uint32_t* r, uint32_t addr) {
    asm volatile("ldmatrix.sync.aligned.m8n8.x4.shared.b16 {%0,%1,%2,%3}, [%4];"
                 : "=r"(r[0]), "=r"(r[1]), "=r"(r[2]), "=r"(r[3]) : "r"(addr));
}
__device__ __forceinline__ void ldsm_x2(uint32_t* r, uint32_t addr) {
    asm volatile("ldmatrix.sync.aligned.m8n8.x2.shared.b16 {%0,%1}, [%2];"
                 : "=r"(r[0]), "=r"(r[1]) : "r"(addr));
}
__device__ __forceinline__ void mma_tf32(float* c, const uint32_t* a, const uint32_t* b) {
    asm volatile(
        "mma.sync.aligned.m16n8k8.row.col.f32.tf32.tf32.f32 "
        "{%0,%1,%2,%3}, {%4,%5,%6,%7}, {%8,%9}, {%0,%1,%2,%3};"
        : "+f"(c[0]), "+f"(c[1]), "+f"(c[2]), "+f"(c[3])
        : "r"(a[0]), "r"(a[1]), "r"(a[2]), "r"(a[3]), "r"(b[0]), "r"(b[1]));
}

// ---------------------------------------------------------------------------
// tf32 mma.sync GEMM:  D = A_rows @ B_rows^T  (both [rows][512] K-contiguous)
// CTA tile 128x128, BK=32. 8 warps = 2(m) x 4(n), warp tile 64x32.
// MODE 0: D[m][n] -> head layout [b,h,l,hd]   (L rows per batch)
// MODE 1: D[m][n] -> row-major + bias[n] + resid[m,n]
// TF32OUT: round stored outputs to tf32 (for downstream HMMA consumption)
// ---------------------------------------------------------------------------
#define PITCH 36

template <int MODE, int TF32OUT>
__global__ void __launch_bounds__(256, 2)
gemm_mma(const float* __restrict__ A, const float* __restrict__ Bm,
         float* __restrict__ Y, int L,
         const float* __restrict__ bias, const float* __restrict__ resid)
{
    __shared__ __align__(16) float As[128 * PITCH];
    __shared__ __align__(16) float Bs[128 * PITCH];

    const int tid  = threadIdx.x;
    const int lane = tid & 31;
    const int wid  = tid >> 5;
    const int wm   = wid & 1;
    const int wn   = wid >> 1;
    const int m0   = blockIdx.x * 128;
    const int n0   = blockIdx.y * 128;

    const uint32_t sA = smem_u32(As);
    const uint32_t sB = smem_u32(Bs);

    const int lrA = (lane & 7) + ((lane >> 3) & 1) * 8;
    const int koA = (lane >> 4) * 16;
    const int lB  = lane & 15;
    const int lrB = lB & 7;
    const int koB = (lB >> 3) * 16;

    const int lrow = tid >> 1;
    const int lcol = (tid & 1) * 16;

    float c[4][4][4];
#pragma unroll
    for (int i = 0; i < 4; i++)
#pragma unroll
        for (int j = 0; j < 4; j++)
#pragma unroll
            for (int e = 0; e < 4; e++) c[i][j][e] = 0.f;

    const float* aptr = A  + (size_t)(m0 + lrow) * E_ + lcol;
    const float* bptr = Bm + (size_t)(n0 + lrow) * E_ + lcol;
    float* asw = &As[lrow * PITCH + lcol];
    float* bsw = &Bs[lrow * PITCH + lcol];

    for (int kt = 0; kt < 16; kt++) {
#pragma unroll
        for (int i4 = 0; i4 < 4; i4++) {
            float4 va = *(const float4*)(aptr + kt * 32 + i4 * 4);
            uint4 ta;
            ta.x = cvt_tf32(va.x); ta.y = cvt_tf32(va.y);
            ta.z = cvt_tf32(va.z); ta.w = cvt_tf32(va.w);
            *(uint4*)(asw + i4 * 4) = ta;
            float4 vb = *(const float4*)(bptr + kt * 32 + i4 * 4);
            uint4 tb;
            tb.x = cvt_tf32(vb.x); tb.y = cvt_tf32(vb.y);
            tb.z = cvt_tf32(vb.z); tb.w = cvt_tf32(vb.w);
            *(uint4*)(bsw + i4 * 4) = tb;
        }
        __syncthreads();

#pragma unroll
        for (int ks = 0; ks < 4; ks++) {
            uint32_t a[4][4], b[4][2];
#pragma unroll
            for (int i = 0; i < 4; i++)
                ldsm_x4(a[i], sA + (uint32_t)(((wm * 64 + i * 16 + lrA) * PITCH + ks * 8) * 4 + koA));
#pragma unroll
            for (int j = 0; j < 4; j++)
                ldsm_x2(b[j], sB + (uint32_t)(((wn * 32 + j * 8 + lrB) * PITCH + ks * 8) * 4 + koB));
#pragma unroll
            for (int i = 0; i < 4; i++)
#pragma unroll
                for (int j = 0; j < 4; j++)
                    mma_tf32(c[i][j], a[i], b[j]);
        }
        __syncthreads();
    }

    const int rq = lane >> 2;
    const int cq = (lane & 3) * 2;

#pragma unroll
    for (int i = 0; i < 4; i++) {
#pragma unroll
        for (int j = 0; j < 4; j++) {
#pragma unroll
            for (int half = 0; half < 2; half++) {
                float v0 = c[i][j][half * 2 + 0];
                float v1 = c[i][j][half * 2 + 1];
                if (TF32OUT) {
                    v0 = __uint_as_float(cvt_tf32(v0));
                    v1 = __uint_as_float(cvt_tf32(v1));
                }
                int m = m0 + wm * 64 + i * 16 + rq + half * 8;
                int n = n0 + wn * 32 + j * 8 + cq;
                if (MODE == 0) {
                    int bb = m / L, l = m - bb * L;
                    int h = n >> 6, hd = n & 63;
                    *(float2*)&Y[(((size_t)(bb * H_ + h) * L + l) << 6) + hd] =
                        make_float2(v0, v1);
                } else {
                    float2 bi2 = *(const float2*)&bias[n];
                    float2 r2  = *(const float2*)&resid[(size_t)m * E_ + n];
                    *(float2*)&Y[(size_t)m * E_ + n] =
                        make_float2(v0 + bi2.x + r2.x, v1 + bi2.y + r2.y);
                }
            }
        }
    }
}

// ---------------------------------------------------------------------------
// Attention v4: block = (b, h, 16 queries), 512 threads (16 warps).
// Phase 1: QK scores via tf32 mma.sync. Warp w owns keys [128w, 128w+128):
//          Q frags (8 ksteps) ldmatrix'd once; B frags loaded straight from
//          global K rows (lane l -> K[n0+l/4][k0+l%4], +4). -> smem scores
// Phase 2: warp-per-query softmax stats + top-20 (chunked lane maxima)
// Phase 3: sparse AV gather (16q x 64d, float4 per thread)
// ---------------------------------------------------------------------------
#define SPITCH 2056   // 2048 + 8 floats: 32B row skew, conflict-free stores

__global__ void __launch_bounds__(512, 1) attn_topk4()
{
    extern __shared__ float sm[];
    float* scores = sm;                        // 16 * SPITCH
    float* Qs     = sm + 16 * SPITCH;          // 16 * 68
    float* swl    = Qs + 16 * 68;              // 16*20 weights
    int*   sil    = (int*)(swl + 320);         // 16*20 indices

    const int tid  = threadIdx.x;
    const int lane = tid & 31;
    const int wid  = tid >> 5;                 // 0..15
    const int q0   = blockIdx.x * 16;
    const int h    = blockIdx.y;
    const int b    = blockIdx.z;
    const int bh   = b * H_ + h;

    // ---- load Q tile (16x64, scaled; already tf32-rounded in g_Qh) ----
    {
        const float* qsrc = g_Qh + ((size_t)bh * LQ_ + q0) * 64;
        for (int i = tid; i < 1024; i += 512) {
            int r = i >> 6, cc = i & 63;
            Qs[r * 68 + cc] = qsrc[i] * 0.125f;   // 1/sqrt(64), exact pow2
        }
    }
    __syncthreads();

    // ---- Phase 1: tf32 mma QK ----
    {
        const uint32_t sQ = smem_u32(Qs);
        const int lrA = (lane & 7) + ((lane >> 3) & 1) * 8;
        const int koA = (lane >> 4) * 16;

        uint32_t aq[8][4];
#pragma unroll
        for (int ks = 0; ks < 8; ks++)
            ldsm_x4(aq[ks], sQ + (uint32_t)((lrA * 68 + ks * 8) * 4 + koA));

        const float* kb = g_Kh + ((size_t)bh * LK_ + wid * 128 + (lane >> 2)) * 64 + (lane & 3);
        const int qrow = lane >> 2;
        const int kc0  = wid * 128 + (lane & 3) * 2;

#pragma unroll 1
        for (int nt = 0; nt < 16; nt++) {
            const float* bp = kb + nt * 512;   // +8 keys * 64 floats
            float c4[4] = {0.f, 0.f, 0.f, 0.f};
#pragma unroll
            for (int ks = 0; ks < 8; ks++) {
                uint32_t bfr[2];
                bfr[0] = __float_as_uint(bp[ks * 8]);
                bfr[1] = __float_as_uint(bp[ks * 8 + 4]);
                mma_tf32(c4, aq[ks], bfr);
            }
            int kc = kc0 + nt * 8;
            *(float2*)&scores[qrow * SPITCH + kc]       = make_float2(c4[0], c4[1]);
            *(float2*)&scores[(qrow + 8) * SPITCH + kc] = make_float2(c4[2], c4[3]);
        }
    }
    __syncthreads();

    // ---- Phase 2: per-warp softmax stats + top-20 for query q = wid ----
    {
        float* row = scores + wid * SPITCH;

        float cm[4]; int ci[4];
        float m = -INFINITY;
#pragma unroll
        for (int c = 0; c < 4; c++) {
            float bv = -INFINITY; int bi = 0;
            for (int i = 0; i < 16; i++) {
                int k = lane + 32 * (c * 16 + i);
                float v = row[k];
                if (v > bv) { bv = v; bi = k; }
            }
            cm[c] = bv; ci[c] = bi;
            m = fmaxf(m, bv);
        }
#pragma unroll
        for (int o = 16; o; o >>= 1) m = fmaxf(m, __shfl_xor_sync(0xffffffffu, m, o));

        float s = 0.f;
        for (int i = 0; i < 64; i++) s += __expf(row[lane + 32 * i] - m);
#pragma unroll
        for (int o = 16; o; o >>= 1) s += __shfl_xor_sync(0xffffffffu, s, o);
        const float inv = 1.f / s;

        for (int t = 0; t < TOPK_; t++) {
            float lv = cm[0]; int li = ci[0];
#pragma unroll
            for (int c = 1; c < 4; c++)
                if (cm[c] > lv || (cm[c] == lv && ci[c] < li)) { lv = cm[c]; li = ci[c]; }
            float bv = lv; int bi = li;
#pragma unroll
            for (int o = 16; o; o >>= 1) {
                float ov = __shfl_xor_sync(0xffffffffu, bv, o);
                int   oi = __shfl_xor_sync(0xffffffffu, bi, o);
                if (ov > bv || (ov == bv && oi < bi)) { bv = ov; bi = oi; }
            }
            if (lane == 0) {
                swl[wid * TOPK_ + t] = __expf(bv - m) * inv;
                sil[wid * TOPK_ + t] = bi;
            }
            if ((bi & 31) == lane) {
                row[bi] = -INFINITY;
                int cc = (bi - lane) >> 9;
#pragma unroll
                for (int c = 0; c < 4; c++) {
                    if (c == cc) {
                        float nv = -INFINITY; int ni = 0;
                        for (int i = 0; i < 16; i++) {
                            int k = lane + 32 * (c * 16 + i);
                            float v = row[k];
                            if (v > nv) { nv = v; ni = k; }
                        }
                        cm[c] = nv; ci[c] = ni;
                    }
                }
            }
            __syncwarp();
        }
    }
    __syncthreads();

    // ---- Phase 3: sparse AV. 256 threads: (q, 4-dim chunk) each ----
    if (tid < 256) {
        int q = tid >> 4;
        int d = (tid & 15) * 4;
        const float* vb = g_Vh + (size_t)bh * LK_ * 64;
        float4 o = make_float4(0.f, 0.f, 0.f, 0.f);
#pragma unroll
        for (int t = 0; t < TOPK_; t++) {
            float w  = swl[q * TOPK_ + t];
            int  idx = sil[q * TOPK_ + t];
            float4 vv = *(const float4*)(vb + (size_t)idx * 64 + d);
            o.x = fmaf(w, vv.x, o.x);
            o.y = fmaf(w, vv.y, o.y);
            o.z = fmaf(w, vv.z, o.z);
            o.w = fmaf(w, vv.w, o.w);
        }
        *(float4*)&g_AO[((size_t)b * LQ_ + q0 + q) * E_ + h * 64 + d] = o;
    }
}

// ---------------------------------------------------------------------------
extern "C" void kernel_launch(void* const* d_in, const int* in_sizes, int n_in,
                              void* d_out, int out_size)
{
    const float* q  = (const float*)d_in[0];
    const float* k  = (const float*)d_in[1];
    const float* v  = (const float*)d_in[2];
    const float* Wq = (const float*)d_in[3];
    const float* Wk = (const float*)d_in[4];
    const float* Wv = (const float*)d_in[5];
    const float* Wo = (const float*)d_in[6];
    const float* bo = (const float*)d_in[7];
    float* out = (float*)d_out;

    float *pQh, *pKh, *pVh, *pAO;
    cudaGetSymbolAddress((void**)&pQh, g_Qh);
    cudaGetSymbolAddress((void**)&pKh, g_Kh);
    cudaGetSymbolAddress((void**)&pVh, g_Vh);
    cudaGetSymbolAddress((void**)&pAO, g_AO);

    const int smem_attn = (16 * SPITCH + 16 * 68 + 320) * 4 + 320 * 4;  // 138496 B
    cudaFuncSetAttribute(attn_topk4, cudaFuncAttributeMaxDynamicSharedMemorySize, smem_attn);

    // projections (tf32 mma.sync); Q/K outputs tf32-rounded for the QK mma
    gemm_mma<0, 1><<<dim3((B_ * LQ_) / 128, 4), 256>>>(q, Wq, pQh, LQ_, nullptr, nullptr);
    gemm_mma<0, 1><<<dim3((B_ * LK_) / 128, 4), 256>>>(k, Wk, pKh, LK_, nullptr, nullptr);
    gemm_mma<0, 0><<<dim3((B_ * LK_) / 128, 4), 256>>>(v, Wv, pVh, LK_, nullptr, nullptr);

    // fused scores (tf32 mma) + softmax + top-20 + sparse AV
    attn_topk4<<<dim3(LQ_ / 16, H_, B_), 512, smem_attn>>>();

    // output projection + bias + residual(q)
    gemm_mma<1, 0><<<dim3((B_ * LQ_) / 128, 4), 256>>>(pAO, Wo, out, LQ_, bo, q);
}